// round 2
// baseline (speedup 1.0000x reference)
#include <cuda_runtime.h>
#include <cstdint>

// Problem constants
#define NQ_IMG   75     // query images
#define NWAY     5
#define NSHOT    5
#define NC       640    // channels (K dim)
#define NHW      441    // 21*21 descriptors per image
#define NS_DESC  2205   // shot*HW class descriptors per way
#define NQ_DESC  33075  // 75*441
#define NSUP_DESC 11025 // 25*441

#define BM 64
#define BN 64
#define BK 16
#define M_TILES 7       // ceil(441/64)
#define N_TILES 35      // ceil(2205/64)
#define NBLOCKS (NQ_IMG * NWAY * M_TILES)   // 2625

// Scratch (no cudaMalloc allowed)
__device__ float d_invq[NQ_DESC];
__device__ float d_invs[NSUP_DESC];
__device__ float d_part[NBLOCKS];

// ---------------------------------------------------------------------------
// Kernel 1: inverse L2 norm of every descriptor.
// One thread per descriptor; loop over C is coalesced across threads (adjacent
// threads hold adjacent m, which is the contiguous axis of x[img][c][m]).
// ---------------------------------------------------------------------------
__global__ void norms_kernel(const float* __restrict__ x1,
                             const float* __restrict__ x2) {
    int d = blockIdx.x * blockDim.x + threadIdx.x;
    if (d >= NQ_DESC + NSUP_DESC) return;

    const float* base;
    float* dst;
    if (d < NQ_DESC) {
        int img = d / NHW, m = d % NHW;
        base = x1 + (size_t)img * NC * NHW + m;
        dst = &d_invq[d];
    } else {
        int e = d - NQ_DESC;
        int img = e / NHW, m = e % NHW;
        base = x2 + (size_t)img * NC * NHW + m;
        dst = &d_invs[e];
    }
    float s = 0.f;
#pragma unroll 8
    for (int c = 0; c < NC; c++) {
        float v = base[(size_t)c * NHW];
        s += v * v;
    }
    *dst = rsqrtf(s);
}

// ---------------------------------------------------------------------------
// Top-3 insertion (a >= b >= c)
// ---------------------------------------------------------------------------
__device__ __forceinline__ void ins3(float v, float& a, float& b, float& c) {
    if (v > c) {
        if (v > a)      { c = b; b = a; a = v; }
        else if (v > b) { c = b; b = v; }
        else            { c = v; }
    }
}

// ---------------------------------------------------------------------------
// Kernel 2: fused cosine-sim GEMM + per-row top-3 + sum.
// Block = (q, w, m_tile). 256 threads, 64x64x16 smem tiles, 4x4 micro-tile.
// ---------------------------------------------------------------------------
__global__ void __launch_bounds__(256, 3)
sim_topk_kernel(const float* __restrict__ x1, const float* __restrict__ x2) {
    const int bid  = blockIdx.x;          // 0..2624
    const int pair = bid / M_TILES;
    const int mt   = bid % M_TILES;
    const int q    = pair / NWAY;
    const int w    = pair % NWAY;

    const int tid = threadIdx.x;
    const int tx  = tid & 15;             // column group (16)
    const int ty  = tid >> 4;             // row group (16)

    __shared__ float As[BK][BM];
    __shared__ float Bs[BK][BN];
    __shared__ float merge[BM][49];       // 48 candidates per row (+pad)
    __shared__ float partial[BM];

    const int m0 = mt * BM;

    // Per-block base pointers
    const float* Abase = x1 + (size_t)q * NC * NHW;            // [640][441]
    const float* Bbase = x2 + (size_t)(w * NSHOT) * NC * NHW;  // 5 imgs [640][441]

    // This thread's loader lane: element (lk group, col am) of the tile
    const int am = tid & 63;              // tile row index for both A and B loads
    const int ak = tid >> 6;              // 0..3, k sub-row

    // A loader pointer (fixed per block)
    const int amm = m0 + am;
    const bool a_ok = (amm < NHW);
    const float* Aptr = Abase + (a_ok ? amm : 0);

    // Per-thread running top-3 for 4 owned rows
    float t0[4], t1[4], t2[4];
#pragma unroll
    for (int r = 0; r < 4; r++) { t0[r] = t1[r] = t2[r] = -1e30f; }

    // Pre-load inverse query norms for owned rows
    float iq[4];
#pragma unroll
    for (int r = 0; r < 4; r++) {
        int mm = m0 + ty * 4 + r;
        iq[r] = (mm < NHW) ? d_invq[q * NHW + mm] : 0.f;
    }

    for (int nt = 0; nt < N_TILES; nt++) {
        const int n0 = nt * BN;

        // B loader pointer for this n-tile (column n0+am)
        const int nn = n0 + am;
        const bool b_ok = (nn < NS_DESC);
        int sShot = nn / NHW;
        int mm2   = nn - sShot * NHW;
        const float* Bptr = b_ok ? (Bbase + ((size_t)sShot * NC) * NHW + mm2)
                                 : Bbase;

        float acc[4][4];
#pragma unroll
        for (int r = 0; r < 4; r++)
#pragma unroll
            for (int j = 0; j < 4; j++) acc[r][j] = 0.f;

        for (int k0 = 0; k0 < NC; k0 += BK) {
#pragma unroll
            for (int i = 0; i < 4; i++) {
                int k = ak * 4 + i;
                As[k][am] = a_ok ? Aptr[(size_t)(k0 + k) * NHW] : 0.f;
                Bs[k][am] = b_ok ? Bptr[(size_t)(k0 + k) * NHW] : 0.f;
            }
            __syncthreads();

#pragma unroll
            for (int k = 0; k < BK; k++) {
                float4 av = *reinterpret_cast<const float4*>(&As[k][ty * 4]);
                float4 bv = *reinterpret_cast<const float4*>(&Bs[k][tx * 4]);
                float a[4] = {av.x, av.y, av.z, av.w};
                float b[4] = {bv.x, bv.y, bv.z, bv.w};
#pragma unroll
                for (int r = 0; r < 4; r++)
#pragma unroll
                    for (int j = 0; j < 4; j++)
                        acc[r][j] = fmaf(a[r], b[j], acc[r][j]);
            }
            __syncthreads();
        }

        // Scale to cosine sims and update running top-3
#pragma unroll
        for (int r = 0; r < 4; r++) {
            int mm = m0 + ty * 4 + r;
            if (mm >= NHW) continue;
#pragma unroll
            for (int j = 0; j < 4; j++) {
                int ncol = n0 + tx * 4 + j;
                if (ncol >= NS_DESC) continue;
                float v = acc[r][j] * iq[r] * d_invs[w * NS_DESC + ncol];
                ins3(v, t0[r], t1[r], t2[r]);
            }
        }
    }

    // Merge: each row has 16 thread-local top-3 sets -> 48 candidates
#pragma unroll
    for (int r = 0; r < 4; r++) {
        int row = ty * 4 + r;
        merge[row][tx * 3 + 0] = t0[r];
        merge[row][tx * 3 + 1] = t1[r];
        merge[row][tx * 3 + 2] = t2[r];
    }
    __syncthreads();

    if (tid < BM) {
        float a = -1e30f, b = -1e30f, c = -1e30f;
        int mm = m0 + tid;
        if (mm < NHW) {
#pragma unroll
            for (int i = 0; i < 48; i++) ins3(merge[tid][i], a, b, c);
            partial[tid] = a + b + c;
        } else {
            partial[tid] = 0.f;
        }
    }
    __syncthreads();

    if (tid == 0) {
        float s = 0.f;
        for (int i = 0; i < BM; i++) s += partial[i];
        d_part[bid] = s;
    }
}

// ---------------------------------------------------------------------------
// Kernel 3: reduce the 7 m-tile partials per (q, w) into the output.
// ---------------------------------------------------------------------------
__global__ void reduce_kernel(float* __restrict__ out) {
    int i = blockIdx.x * blockDim.x + threadIdx.x;
    if (i < NQ_IMG * NWAY) {
        float s = 0.f;
#pragma unroll
        for (int j = 0; j < M_TILES; j++) s += d_part[i * M_TILES + j];
        out[i] = s;
    }
}

// ---------------------------------------------------------------------------
extern "C" void kernel_launch(void* const* d_in, const int* in_sizes, int n_in,
                              void* d_out, int out_size) {
    const float* x1 = (const float*)d_in[0];   // [75, 640, 21, 21]
    const float* x2 = (const float*)d_in[1];   // [25, 640, 21, 21]
    float* out = (float*)d_out;                // [75, 5]

    norms_kernel<<<(NQ_DESC + NSUP_DESC + 255) / 256, 256>>>(x1, x2);
    sim_topk_kernel<<<NBLOCKS, 256>>>(x1, x2);
    reduce_kernel<<<2, 256>>>(out);
}

// round 5
// speedup vs baseline: 5.8991x; 5.8991x over previous
#include <cuda_runtime.h>
#include <cuda_bf16.h>
#include <cstdint>

// ---------------------------------------------------------------------------
// Problem constants
// ---------------------------------------------------------------------------
#define NQ    75      // query images
#define NWAY  5
#define NC    640     // channels (K)
#define NHW   441     // descriptors per image
#define NSD   2205    // class descriptors per way (5 shots * 441)
#define QPAD  512     // padded M per query image (4 tiles of 128)
#define SPAD  2304    // padded N per way (18 tiles of 128)
#define MT    4       // m-tiles of 128
#define NT    18      // n-tiles of 128
#define BK    32
#define KCH   (NC / BK)   // 20 k-chunks
#define SAS   40      // smem row stride in bf16 (32 + 8 pad = 80B, conflict-free ldmatrix)

// ---------------------------------------------------------------------------
// Scratch (device globals; no cudaMalloc allowed)
// ---------------------------------------------------------------------------
__device__ __align__(1024) __nv_bfloat16 d_q[(size_t)NQ * QPAD * NC];
__device__ __align__(1024) __nv_bfloat16 d_s[(size_t)NWAY * SPAD * NC];
__device__ float d_part[NQ * NWAY * MT];

// ---------------------------------------------------------------------------
// Helpers
// ---------------------------------------------------------------------------
__device__ __forceinline__ uint32_t smem_u32(const void* p) {
    uint32_t a;
    asm("{ .reg .u64 t; cvta.to.shared.u64 t, %1; cvt.u32.u64 %0, t; }"
        : "=r"(a) : "l"(p));
    return a;
}
__device__ __forceinline__ void cp16(uint32_t dst, const void* src) {
    asm volatile("cp.async.cg.shared.global [%0], [%1], 16;" :: "r"(dst), "l"(src));
}
#define CP_COMMIT() asm volatile("cp.async.commit_group;" ::: "memory")
#define CP_WAIT(n)  asm volatile("cp.async.wait_group %0;" :: "n"(n) : "memory")

__device__ __forceinline__ void ldsm_x4(uint32_t& r0, uint32_t& r1, uint32_t& r2,
                                        uint32_t& r3, uint32_t a) {
    asm volatile("ldmatrix.sync.aligned.m8n8.x4.shared.b16 {%0,%1,%2,%3}, [%4];"
                 : "=r"(r0), "=r"(r1), "=r"(r2), "=r"(r3) : "r"(a));
}
__device__ __forceinline__ void mma16816(float* c, uint32_t a0, uint32_t a1,
                                         uint32_t a2, uint32_t a3,
                                         uint32_t b0, uint32_t b1) {
    asm volatile(
        "mma.sync.aligned.m16n8k16.row.col.f32.bf16.bf16.f32 "
        "{%0,%1,%2,%3}, {%4,%5,%6,%7}, {%8,%9}, {%0,%1,%2,%3};"
        : "+f"(c[0]), "+f"(c[1]), "+f"(c[2]), "+f"(c[3])
        : "r"(a0), "r"(a1), "r"(a2), "r"(a3), "r"(b0), "r"(b1));
}
__device__ __forceinline__ void ins3(float v, float& a, float& b, float& c) {
    if (v > c) {
        if (v > a)      { c = b; b = a; a = v; }
        else if (v > b) { c = b; b = v; }
        else            { c = v; }
    }
}

// ---------------------------------------------------------------------------
// Kernel 0: zero the bf16 scratch (padding must be exactly 0)
// ---------------------------------------------------------------------------
__global__ void zero_kernel() {
    const size_t nq4 = sizeof(d_q) / 16, ns4 = sizeof(d_s) / 16;
    uint4 z = make_uint4(0, 0, 0, 0);
    for (size_t i = (size_t)blockIdx.x * blockDim.x + threadIdx.x;
         i < nq4 + ns4; i += (size_t)gridDim.x * blockDim.x) {
        if (i < nq4) ((uint4*)d_q)[i] = z;
        else         ((uint4*)d_s)[i - nq4] = z;
    }
}

// ---------------------------------------------------------------------------
// Kernel 1: fused L2-normalize + transpose [C,HW]->[HW,C] + bf16 convert.
// One block per (image, 64-row m-tile). 75*7 query blocks + 25*7 support.
// ---------------------------------------------------------------------------
__global__ void __launch_bounds__(256) convert_kernel(const float* __restrict__ x1,
                                                      const float* __restrict__ x2) {
    int bid = blockIdx.x;
    const float* src;
    __nv_bfloat16* dst;
    int m0;
    if (bid < 525) {
        int img = bid / 7; m0 = (bid % 7) * 64;
        src = x1 + (size_t)img * NC * NHW;
        dst = d_q + (size_t)img * QPAD * NC;
    } else {
        int sid = bid - 525;
        int img = sid / 7; m0 = (sid % 7) * 64;
        int w = img / 5, sh = img % 5;
        src = x2 + (size_t)img * NC * NHW;
        dst = d_s + ((size_t)w * SPAD + (size_t)sh * NHW) * NC;
    }
    int tid = threadIdx.x;
    int mx = tid & 63, cy = tid >> 6;

    __shared__ float sp[4][64];
    __shared__ float sinv[64];
    __shared__ __nv_bfloat16 st[64][72];   // padded to break bank conflicts

    float acc = 0.f;
    if (m0 + mx < NHW) {
        for (int c = cy; c < NC; c += 4) {
            float v = src[(size_t)c * NHW + m0 + mx];
            acc = fmaf(v, v, acc);
        }
    }
    sp[cy][mx] = acc;
    __syncthreads();
    if (tid < 64)
        sinv[tid] = rsqrtf(sp[0][tid] + sp[1][tid] + sp[2][tid] + sp[3][tid]);
    __syncthreads();

    int mr = tid >> 2, qt = tid & 3;
    for (int c0 = 0; c0 < NC; c0 += 64) {
#pragma unroll
        for (int j = 0; j < 16; j++) {
            int idx = j * 256 + tid;
            int cl = idx >> 6, mm = idx & 63;
            float v = (m0 + mm < NHW) ? src[(size_t)(c0 + cl) * NHW + m0 + mm] : 0.f;
            st[mm][cl] = __float2bfloat16(v * sinv[mm]);
        }
        __syncthreads();
        if (m0 + mr < NHW) {
            __nv_bfloat16 tmp[16];
#pragma unroll
            for (int i = 0; i < 16; i++) tmp[i] = st[mr][qt * 16 + i];
            __nv_bfloat16* drow = dst + (size_t)(m0 + mr) * NC + c0 + qt * 16;
            ((uint4*)drow)[0] = ((uint4*)tmp)[0];
            ((uint4*)drow)[1] = ((uint4*)tmp)[1];
        }
        __syncthreads();
    }
}

// ---------------------------------------------------------------------------
// Kernel 2: bf16 mma.sync GEMM (128x128x640 per n-tile) + fused top-3 + sum.
// CTA = (q, w, mtile). 256 threads = 2 warpM x 4 warpN, warp tile 64x32.
// BK=32 double-buffered via cp.async. Top-3 tracked per row in registers.
// ---------------------------------------------------------------------------
__global__ void __launch_bounds__(256) sim_kernel() {
    __shared__ __nv_bfloat16 sA[2][128][SAS];
    __shared__ __nv_bfloat16 sB[2][128][SAS];
    __shared__ float smerge[128][4][3];
    __shared__ float swsum[8];

    const int bid  = blockIdx.x;
    const int mt   = bid & 3;
    const int pair = bid >> 2;
    const int w    = pair % NWAY;
    const int q    = pair / NWAY;
    const int tid  = threadIdx.x;
    const int wid  = tid >> 5;
    const int lane = tid & 31;
    const int warpM = wid & 1;          // 0..1  (64-row halves)
    const int warpN = wid >> 1;         // 0..3  (32-col quarters)
    const int g    = lane >> 2;
    const int tig  = lane & 3;

    const __nv_bfloat16* Ab = d_q + ((size_t)q * QPAD + (size_t)mt * 128) * NC;
    const __nv_bfloat16* Bbase = d_s + (size_t)w * SPAD * NC;

    const uint32_t sbA = smem_u32(&sA[0][0][0]);
    const uint32_t sbB = smem_u32(&sB[0][0][0]);

    // Loader lanes: 512 16B-chunks per tile, 2 per thread per tile
    const int lrow0 = tid >> 2, lc0 = (tid & 3) * 8;           // chunk tid
    const int lrow1 = (tid + 256) >> 2, lc1 = lc0;             // chunk tid+256

    // ldmatrix source addresses (stage 0 base; stage adds 128*SAS*2)
    const uint32_t stageB = 128 * SAS * 2;
    // A: row = warpM*64 + mf*16 + (lane&15), col = ks*16 + (lane>>4)*8
    const int arow = warpM * 64 + (lane & 15);
    const int acol = (lane >> 4) * 8;
    // B: n = warpN*32 + h*16 + ((lane>>4)<<3) + (lane&7), col = ks*16 + ((lane>>3)&1)*8
    const int brow = warpN * 32 + ((lane >> 4) << 3) + (lane & 7);
    const int bcol = ((lane >> 3) & 1) * 8;

    // Running top-3 per owned row-slot: slot = mf*2 + rg, row = mf*16 + rg*8 + g
    float t0[8], t1[8], t2[8];
#pragma unroll
    for (int s = 0; s < 8; s++) { t0[s] = t1[s] = t2[s] = -1e30f; }

    for (int nt = 0; nt < NT; nt++) {
        const __nv_bfloat16* Bb = Bbase + (size_t)nt * 128 * NC;

        float acc[4][4][4];
#pragma unroll
        for (int mf = 0; mf < 4; mf++)
#pragma unroll
            for (int nf = 0; nf < 4; nf++)
#pragma unroll
                for (int j = 0; j < 4; j++) acc[mf][nf][j] = 0.f;

        // prologue: stage 0 <- chunk 0
        {
            uint32_t dA = sbA + (uint32_t)(lrow0 * SAS + lc0) * 2;
            uint32_t dB = sbB + (uint32_t)(lrow0 * SAS + lc0) * 2;
            cp16(dA, Ab + (size_t)lrow0 * NC + lc0);
            cp16(dB, Bb + (size_t)lrow0 * NC + lc0);
            dA = sbA + (uint32_t)(lrow1 * SAS + lc1) * 2;
            dB = sbB + (uint32_t)(lrow1 * SAS + lc1) * 2;
            cp16(dA, Ab + (size_t)lrow1 * NC + lc1);
            cp16(dB, Bb + (size_t)lrow1 * NC + lc1);
            CP_COMMIT();
        }

        for (int kc = 0; kc < KCH; kc++) {
            const int cs = kc & 1;
            if (kc + 1 < KCH) {
                const int ns = cs ^ 1;
                const int k0 = (kc + 1) * BK;
                uint32_t so = ns * stageB;
                cp16(sbA + so + (uint32_t)(lrow0 * SAS + lc0) * 2,
                     Ab + (size_t)lrow0 * NC + k0 + lc0);
                cp16(sbB + so + (uint32_t)(lrow0 * SAS + lc0) * 2,
                     Bb + (size_t)lrow0 * NC + k0 + lc0);
                cp16(sbA + so + (uint32_t)(lrow1 * SAS + lc1) * 2,
                     Ab + (size_t)lrow1 * NC + k0 + lc1);
                cp16(sbB + so + (uint32_t)(lrow1 * SAS + lc1) * 2,
                     Bb + (size_t)lrow1 * NC + k0 + lc1);
                CP_COMMIT();
                CP_WAIT(1);
            } else {
                CP_WAIT(0);
            }
            __syncthreads();

#pragma unroll
            for (int ks = 0; ks < 2; ks++) {
                uint32_t a0[4], a1[4], a2[4], a3[4];
#pragma unroll
                for (int mf = 0; mf < 4; mf++) {
                    uint32_t addr = sbA + cs * stageB +
                        (uint32_t)((arow + mf * 16) * SAS + ks * 16 + acol) * 2;
                    ldsm_x4(a0[mf], a1[mf], a2[mf], a3[mf], addr);
                }
                uint32_t b[4][2];
#pragma unroll
                for (int h = 0; h < 2; h++) {
                    uint32_t addr = sbB + cs * stageB +
                        (uint32_t)((brow + h * 16) * SAS + ks * 16 + bcol) * 2;
                    uint32_t r0, r1, r2, r3;
                    ldsm_x4(r0, r1, r2, r3, addr);
                    b[h * 2][0] = r0; b[h * 2][1] = r1;
                    b[h * 2 + 1][0] = r2; b[h * 2 + 1][1] = r3;
                }
#pragma unroll
                for (int mf = 0; mf < 4; mf++)
#pragma unroll
                    for (int nf = 0; nf < 4; nf++)
                        mma16816(acc[mf][nf], a0[mf], a1[mf], a2[mf], a3[mf],
                                 b[nf][0], b[nf][1]);
            }
            __syncthreads();
        }

        // Fused epilogue: running top-3. Mask padded N cols (only last n-tile).
        const int climit = (nt == NT - 1) ? (NSD - (NT - 1) * 128) : 1024;  // 29 or all
#pragma unroll
        for (int mf = 0; mf < 4; mf++) {
            const int s0 = mf * 2, s1 = mf * 2 + 1;
#pragma unroll
            for (int nf = 0; nf < 4; nf++) {
                const int colb = warpN * 32 + nf * 8 + tig * 2;
                const bool v0 = colb < climit, v1 = colb + 1 < climit;
                const float* c = acc[mf][nf];
                if (v0) { ins3(c[0], t0[s0], t1[s0], t2[s0]);
                          ins3(c[2], t0[s1], t1[s1], t2[s1]); }
                if (v1) { ins3(c[1], t0[s0], t1[s0], t2[s0]);
                          ins3(c[3], t0[s1], t1[s1], t2[s1]); }
            }
        }
    }

    // Intra-warp merge across the 4 lanes (tig) sharing each row
#pragma unroll
    for (int s = 0; s < 8; s++) {
#pragma unroll
        for (int d = 1; d <= 2; d <<= 1) {
            float m0 = __shfl_xor_sync(0xffffffffu, t0[s], d);
            float m1 = __shfl_xor_sync(0xffffffffu, t1[s], d);
            float m2 = __shfl_xor_sync(0xffffffffu, t2[s], d);
            ins3(m0, t0[s], t1[s], t2[s]);
            ins3(m1, t0[s], t1[s], t2[s]);
            ins3(m2, t0[s], t1[s], t2[s]);
        }
    }
    if (tig == 0) {
#pragma unroll
        for (int s = 0; s < 8; s++) {
            int row = warpM * 64 + (s >> 1) * 16 + (s & 1) * 8 + g;
            smerge[row][warpN][0] = t0[s];
            smerge[row][warpN][1] = t1[s];
            smerge[row][warpN][2] = t2[s];
        }
    }
    __syncthreads();

    // Merge across the 4 N-warps per row; sum top-3; gate padded rows
    float rsum = 0.f;
    if (tid < 128) {
        int grow = mt * 128 + tid;
        if (grow < NHW) {
            float a = -1e30f, b = -1e30f, c = -1e30f;
#pragma unroll
            for (int wn = 0; wn < 4; wn++) {
                ins3(smerge[tid][wn][0], a, b, c);
                ins3(smerge[tid][wn][1], a, b, c);
                ins3(smerge[tid][wn][2], a, b, c);
            }
            rsum = a + b + c;
        }
    }
#pragma unroll
    for (int o = 16; o > 0; o >>= 1) rsum += __shfl_xor_sync(0xffffffffu, rsum, o);
    if (lane == 0) swsum[wid] = rsum;
    __syncthreads();
    if (tid == 0) {
        float s = 0.f;
#pragma unroll
        for (int i = 0; i < 8; i++) s += swsum[i];
        d_part[bid] = s;
    }
}

// ---------------------------------------------------------------------------
// Kernel 3: final reduce over m-tiles
// ---------------------------------------------------------------------------
__global__ void reduce_kernel(float* __restrict__ out) {
    int i = blockIdx.x * blockDim.x + threadIdx.x;
    if (i < NQ * NWAY) {
        out[i] = d_part[i * 4] + d_part[i * 4 + 1] + d_part[i * 4 + 2] + d_part[i * 4 + 3];
    }
}

// ---------------------------------------------------------------------------
extern "C" void kernel_launch(void* const* d_in, const int* in_sizes, int n_in,
                              void* d_out, int out_size) {
    const float* x1 = (const float*)d_in[0];   // [75, 640, 21, 21]
    const float* x2 = (const float*)d_in[1];   // [25, 640, 21, 21]
    float* out = (float*)d_out;                // [75, 5]

    zero_kernel<<<2048, 256>>>();
    convert_kernel<<<700, 256>>>(x1, x2);
    sim_kernel<<<NQ * NWAY * MT, 256>>>();
    reduce_kernel<<<2, 256>>>(out);
}

// round 8
// speedup vs baseline: 6.2953x; 1.0672x over previous
#include <cuda_runtime.h>
#include <cuda_bf16.h>
#include <cstdint>

// ---------------------------------------------------------------------------
// Problem constants
// ---------------------------------------------------------------------------
#define NQ     75      // query images
#define NWAY   5
#define NC     640     // channels (K)
#define NHW    441     // descriptors per image
#define NSD    2205    // class descriptors per way (5 shots * 441)
#define MROWS  33075   // 75*441 packed query rows
#define MTILES 259     // ceil(33075/128)
#define MPAD   (MTILES * 128)   // 33152
#define SPAD   2304    // padded N per way (18 tiles of 128)
#define NT     18      // n-tiles of 128
#define BK     32
#define KCH    (NC / BK)        // 20 k-chunks per n-tile
#define TOTCH  (NT * KCH)       // 360 flattened chunks
#define SAS    40      // smem row stride in bf16 (32 + 8 pad, conflict-free ldmatrix)

// smem layout (dynamic): 3-stage A ring | 3-stage B ring | merge
#define STG_BYTES (128 * SAS * 2)            // 10240
#define SB_OFF    (3 * STG_BYTES)            // 30720
#define MERGE_OFF (6 * STG_BYTES)            // 61440
#define SMEM_TOTAL (MERGE_OFF + 128 * 4 * 3 * 4 + 64)   // ~67.6KB

// ---------------------------------------------------------------------------
// Scratch (device globals; no cudaMalloc allowed)
// ---------------------------------------------------------------------------
__device__ __align__(1024) __nv_bfloat16 d_q[(size_t)MPAD * NC];
__device__ __align__(1024) __nv_bfloat16 d_s[(size_t)NWAY * SPAD * NC];
__device__ float d_rowsum[(size_t)NWAY * MPAD];

// ---------------------------------------------------------------------------
// Helpers
// ---------------------------------------------------------------------------
__device__ __forceinline__ uint32_t smem_u32(const void* p) {
    uint32_t a;
    asm("{ .reg .u64 t; cvta.to.shared.u64 t, %1; cvt.u32.u64 %0, t; }"
        : "=r"(a) : "l"(p));
    return a;
}
__device__ __forceinline__ void cp16(uint32_t dst, const void* src) {
    asm volatile("cp.async.cg.shared.global [%0], [%1], 16;" :: "r"(dst), "l"(src));
}
#define CP_COMMIT() asm volatile("cp.async.commit_group;" ::: "memory")
#define CP_WAIT(n)  asm volatile("cp.async.wait_group %0;" :: "n"(n) : "memory")

__device__ __forceinline__ void ldsm_x4(uint32_t& r0, uint32_t& r1, uint32_t& r2,
                                        uint32_t& r3, uint32_t a) {
    asm volatile("ldmatrix.sync.aligned.m8n8.x4.shared.b16 {%0,%1,%2,%3}, [%4];"
                 : "=r"(r0), "=r"(r1), "=r"(r2), "=r"(r3) : "r"(a));
}
__device__ __forceinline__ void mma16816(float* c, uint32_t a0, uint32_t a1,
                                         uint32_t a2, uint32_t a3,
                                         uint32_t b0, uint32_t b1) {
    asm volatile(
        "mma.sync.aligned.m16n8k16.row.col.f32.bf16.bf16.f32 "
        "{%0,%1,%2,%3}, {%4,%5,%6,%7}, {%8,%9}, {%0,%1,%2,%3};"
        : "+f"(c[0]), "+f"(c[1]), "+f"(c[2]), "+f"(c[3])
        : "r"(a0), "r"(a1), "r"(a2), "r"(a3), "r"(b0), "r"(b1));
}
__device__ __forceinline__ void ins3(float v, float& a, float& b, float& c) {
    if (v > c) {
        if (v > a)      { c = b; b = a; a = v; }
        else if (v > b) { c = b; b = v; }
        else            { c = v; }
    }
}

// ---------------------------------------------------------------------------
// Kernel 0: zero d_s (N-padding rows must stay inert; cheap insurance)
// ---------------------------------------------------------------------------
__global__ void zero_kernel() {
    const size_t ns4 = sizeof(d_s) / 16;
    uint4 z = make_uint4(0, 0, 0, 0);
    for (size_t i = (size_t)blockIdx.x * blockDim.x + threadIdx.x;
         i < ns4; i += (size_t)gridDim.x * blockDim.x)
        ((uint4*)d_s)[i] = z;
}

// ---------------------------------------------------------------------------
// Kernel 1: fused L2-normalize + transpose [C,HW]->[HW,C] + bf16 convert.
// One block per (image, 64-row m-slab). Queries pack densely (441 rows/img).
// ---------------------------------------------------------------------------
__global__ void __launch_bounds__(256) convert_kernel(const float* __restrict__ x1,
                                                      const float* __restrict__ x2) {
    int bid = blockIdx.x;
    const float* src;
    __nv_bfloat16* dst;
    int m0;
    if (bid < 525) {
        int img = bid / 7; m0 = (bid % 7) * 64;
        src = x1 + (size_t)img * NC * NHW;
        dst = d_q + (size_t)img * NHW * NC;          // packed, no per-image pad
    } else {
        int sid = bid - 525;
        int img = sid / 7; m0 = (sid % 7) * 64;
        int w = img / 5, sh = img % 5;
        src = x2 + (size_t)img * NC * NHW;
        dst = d_s + ((size_t)w * SPAD + (size_t)sh * NHW) * NC;
    }
    int tid = threadIdx.x;
    int mx = tid & 63, cy = tid >> 6;

    __shared__ float sp[4][64];
    __shared__ float sinv[64];
    __shared__ __nv_bfloat16 st[64][72];

    float acc = 0.f;
    if (m0 + mx < NHW) {
        for (int c = cy; c < NC; c += 4) {
            float v = src[(size_t)c * NHW + m0 + mx];
            acc = fmaf(v, v, acc);
        }
    }
    sp[cy][mx] = acc;
    __syncthreads();
    if (tid < 64)
        sinv[tid] = rsqrtf(sp[0][tid] + sp[1][tid] + sp[2][tid] + sp[3][tid]);
    __syncthreads();

    int mr = tid >> 2, qt = tid & 3;
    for (int c0 = 0; c0 < NC; c0 += 64) {
#pragma unroll
        for (int j = 0; j < 16; j++) {
            int idx = j * 256 + tid;
            int cl = idx >> 6, mm = idx & 63;
            float v = (m0 + mm < NHW) ? src[(size_t)(c0 + cl) * NHW + m0 + mm] : 0.f;
            st[mm][cl] = __float2bfloat16(v * sinv[mm]);
        }
        __syncthreads();
        if (m0 + mr < NHW) {
            __nv_bfloat16 tmp[16];
#pragma unroll
            for (int i = 0; i < 16; i++) tmp[i] = st[mr][qt * 16 + i];
            __nv_bfloat16* drow = dst + (size_t)(m0 + mr) * NC + c0 + qt * 16;
            ((uint4*)drow)[0] = ((uint4*)tmp)[0];
            ((uint4*)drow)[1] = ((uint4*)tmp)[1];
        }
        __syncthreads();
    }
}

// ---------------------------------------------------------------------------
// Kernel 2: bf16 mma.sync GEMM + fused top-3 + per-row sum.
// CTA = (mtile, w). 256 threads = 2 warpM x 4 warpN, warp tile 64x32.
// Flattened 360-chunk stream, 3-stage cp.async ring, ONE sync per chunk.
// ---------------------------------------------------------------------------
__global__ void __launch_bounds__(256) sim_kernel() {
    extern __shared__ char smem[];
    const uint32_t sbA = smem_u32(smem);
    const uint32_t sbB = sbA + SB_OFF;
    float (*smerge)[4][3] = (float(*)[4][3])(smem + MERGE_OFF);

    const int bid   = blockIdx.x;
    const int w     = bid % NWAY;
    const int mtile = bid / NWAY;
    const int tid   = threadIdx.x;
    const int wid   = tid >> 5;
    const int lane  = tid & 31;
    const int warpM = wid & 1;
    const int warpN = wid >> 1;
    const int g8    = lane >> 2;
    const int tig   = lane & 3;

    const __nv_bfloat16* Ab = d_q + (size_t)mtile * 128 * NC;
    const __nv_bfloat16* Bw = d_s + (size_t)w * SPAD * NC;

    // loader mapping: per array 512 16B-vectors per chunk; 2 per thread
    const int v0r = tid >> 2,           v0c = (tid & 3) * 8;
    const int v1r = (tid + 256) >> 2,   v1c = v0c;

    // ldmatrix source coords
    const int arow = warpM * 64 + (lane & 15);
    const int acol = (lane >> 4) * 8;
    const int brow = warpN * 32 + ((lane >> 4) << 3) + (lane & 7);
    const int bcol = ((lane >> 3) & 1) * 8;

    float t0[8], t1[8], t2[8];
#pragma unroll
    for (int s = 0; s < 8; s++) { t0[s] = t1[s] = t2[s] = -1e30f; }

    float acc[4][4][4];

    // issue chunk g2 into stage g2%3 (always commit, even if empty)
    auto issue = [&](int g2) {
        if (g2 < TOTCH) {
            int nt2 = g2 / KCH, kc2 = g2 - nt2 * KCH;
            uint32_t so = (uint32_t)(g2 % 3) * STG_BYTES;
            const __nv_bfloat16* As = Ab + kc2 * BK;
            const __nv_bfloat16* Bs = Bw + (size_t)nt2 * 128 * NC + kc2 * BK;
            cp16(sbA + so + (uint32_t)(v0r * SAS + v0c) * 2, As + (size_t)v0r * NC + v0c);
            cp16(sbA + so + (uint32_t)(v1r * SAS + v1c) * 2, As + (size_t)v1r * NC + v1c);
            cp16(sbB + so + (uint32_t)(v0r * SAS + v0c) * 2, Bs + (size_t)v0r * NC + v0c);
            cp16(sbB + so + (uint32_t)(v1r * SAS + v1c) * 2, Bs + (size_t)v1r * NC + v1c);
        }
        CP_COMMIT();
    };

    issue(0);
    issue(1);

    for (int g = 0; g < TOTCH; g++) {
        const int nt = g / KCH;
        const int kc = g - nt * KCH;
        const uint32_t cso = (uint32_t)(g % 3) * STG_BYTES;

        CP_WAIT(1);            // chunk g landed (2 committed after it at most)
        __syncthreads();       // all warps done with stage (g-1)%3 == (g+2)%3
        issue(g + 2);

        if (kc == 0) {
#pragma unroll
            for (int mf = 0; mf < 4; mf++)
#pragma unroll
                for (int nf = 0; nf < 4; nf++)
#pragma unroll
                    for (int j = 0; j < 4; j++) acc[mf][nf][j] = 0.f;
        }

#pragma unroll
        for (int ks = 0; ks < 2; ks++) {
            uint32_t a0[4], a1[4], a2[4], a3[4];
#pragma unroll
            for (int mf = 0; mf < 4; mf++) {
                uint32_t addr = sbA + cso +
                    (uint32_t)((arow + mf * 16) * SAS + ks * 16 + acol) * 2;
                ldsm_x4(a0[mf], a1[mf], a2[mf], a3[mf], addr);
            }
            uint32_t b[4][2];
#pragma unroll
            for (int h = 0; h < 2; h++) {
                uint32_t addr = sbB + cso +
                    (uint32_t)((brow + h * 16) * SAS + ks * 16 + bcol) * 2;
                uint32_t r0, r1, r2, r3;
                ldsm_x4(r0, r1, r2, r3, addr);
                b[h * 2][0] = r0;     b[h * 2][1] = r1;
                b[h * 2 + 1][0] = r2; b[h * 2 + 1][1] = r3;
            }
#pragma unroll
            for (int mf = 0; mf < 4; mf++)
#pragma unroll
                for (int nf = 0; nf < 4; nf++)
                    mma16816(acc[mf][nf], a0[mf], a1[mf], a2[mf], a3[mf],
                             b[nf][0], b[nf][1]);
        }

        if (kc == KCH - 1) {
            // fold this n-tile's sims into running top-3 (mask N padding)
            const int climit = (nt == NT - 1) ? (NSD - (NT - 1) * 128) : 1024;
#pragma unroll
            for (int mf = 0; mf < 4; mf++) {
                const int s0 = mf * 2, s1 = mf * 2 + 1;
#pragma unroll
                for (int nf = 0; nf < 4; nf++) {
                    const int colb = warpN * 32 + nf * 8 + tig * 2;
                    const bool u0 = colb < climit, u1 = colb + 1 < climit;
                    const float* c = acc[mf][nf];
                    if (u0) { ins3(c[0], t0[s0], t1[s0], t2[s0]);
                              ins3(c[2], t0[s1], t1[s1], t2[s1]); }
                    if (u1) { ins3(c[1], t0[s0], t1[s0], t2[s0]);
                              ins3(c[3], t0[s1], t1[s1], t2[s1]); }
                }
            }
        }
    }

    // intra-warp merge across the 4 lanes sharing each row
#pragma unroll
    for (int s = 0; s < 8; s++) {
#pragma unroll
        for (int d = 1; d <= 2; d <<= 1) {
            float m0 = __shfl_xor_sync(0xffffffffu, t0[s], d);
            float m1 = __shfl_xor_sync(0xffffffffu, t1[s], d);
            float m2 = __shfl_xor_sync(0xffffffffu, t2[s], d);
            ins3(m0, t0[s], t1[s], t2[s]);
            ins3(m1, t0[s], t1[s], t2[s]);
            ins3(m2, t0[s], t1[s], t2[s]);
        }
    }
    if (tig == 0) {
#pragma unroll
        for (int s = 0; s < 8; s++) {
            int row = warpM * 64 + (s >> 1) * 16 + (s & 1) * 8 + g8;
            smerge[row][warpN][0] = t0[s];
            smerge[row][warpN][1] = t1[s];
            smerge[row][warpN][2] = t2[s];
        }
    }
    __syncthreads();

    // merge the 4 N-warps per row; write per-row top-3 sum
    if (tid < 128) {
        int grow = mtile * 128 + tid;
        if (grow < MROWS) {
            float a = -1e30f, b = -1e30f, c = -1e30f;
#pragma unroll
            for (int wn = 0; wn < 4; wn++) {
                ins3(smerge[tid][wn][0], a, b, c);
                ins3(smerge[tid][wn][1], a, b, c);
                ins3(smerge[tid][wn][2], a, b, c);
            }
            d_rowsum[(size_t)w * MPAD + grow] = a + b + c;
        }
    }
}

// ---------------------------------------------------------------------------
// Kernel 3: one warp per (q, w) sums its 441 row contributions.
// ---------------------------------------------------------------------------
__global__ void reduce_kernel(float* __restrict__ out) {
    int wi = (blockIdx.x * blockDim.x + threadIdx.x) >> 5;
    int lane = threadIdx.x & 31;
    if (wi >= NQ * NWAY) return;
    int q = wi / NWAY, w = wi % NWAY;
    const float* rs = d_rowsum + (size_t)w * MPAD + (size_t)q * NHW;
    float s = 0.f;
    for (int m = lane; m < NHW; m += 32) s += rs[m];
#pragma unroll
    for (int o = 16; o > 0; o >>= 1) s += __shfl_xor_sync(0xffffffffu, s, o);
    if (lane == 0) out[wi] = s;
}

// ---------------------------------------------------------------------------
extern "C" void kernel_launch(void* const* d_in, const int* in_sizes, int n_in,
                              void* d_out, int out_size) {
    const float* x1 = (const float*)d_in[0];   // [75, 640, 21, 21]
    const float* x2 = (const float*)d_in[1];   // [25, 640, 21, 21]
    float* out = (float*)d_out;                // [75, 5]

    cudaFuncSetAttribute(sim_kernel, cudaFuncAttributeMaxDynamicSharedMemorySize,
                         SMEM_TOTAL);

    zero_kernel<<<512, 256>>>();
    convert_kernel<<<700, 256>>>(x1, x2);
    sim_kernel<<<MTILES * NWAY, 256, SMEM_TOTAL>>>();
    reduce_kernel<<<(NQ * NWAY * 32 + 255) / 256, 256>>>(out);
}

// round 11
// speedup vs baseline: 7.0162x; 1.1145x over previous
#include <cuda_runtime.h>
#include <cuda_bf16.h>
#include <cstdint>

// ---------------------------------------------------------------------------
// Problem constants
// ---------------------------------------------------------------------------
#define NQ     75      // query images
#define NWAY   5
#define NC     640     // channels (K)
#define NHW    441     // descriptors per image
#define NSD    2205    // class descriptors per way (5 shots * 441)
#define MROWS  33075   // 75*441 packed query rows
#define MTILES 259     // ceil(33075/128)
#define MPAD   (MTILES * 128)   // 33152
#define SPAD   2304    // padded N per way (18 tiles of 128)
#define NT     18      // n-tiles of 128
#define BK     64
#define KCH    (NC / BK)        // 10 k-chunks per n-tile
#define TOTCH  (NT * KCH)       // 180 flattened chunks
#define SAS    72      // smem row stride in bf16 (64 + 8 pad, conflict-free ldmatrix)

// smem layout (dynamic): 3-stage A ring | 3-stage B ring | merge
#define STG_BYTES (128 * SAS * 2)              // 18432
#define SB_OFF    (3 * STG_BYTES)              // 55296
#define MERGE_OFF (6 * STG_BYTES)              // 110592
#define SMEM_TOTAL (MERGE_OFF + 128 * 2 * 3 * 4 + 64)   // 113728 (~111KB)

// ---------------------------------------------------------------------------
// Scratch (device globals; no cudaMalloc allowed)
// ---------------------------------------------------------------------------
__device__ __align__(1024) __nv_bfloat16 d_q[(size_t)MPAD * NC];
__device__ __align__(1024) __nv_bfloat16 d_s[(size_t)NWAY * SPAD * NC];
__device__ float d_rowsum[(size_t)NWAY * MPAD];

// ---------------------------------------------------------------------------
// Helpers
// ---------------------------------------------------------------------------
__device__ __forceinline__ uint32_t smem_u32(const void* p) {
    uint32_t a;
    asm("{ .reg .u64 t; cvta.to.shared.u64 t, %1; cvt.u32.u64 %0, t; }"
        : "=r"(a) : "l"(p));
    return a;
}
__device__ __forceinline__ void cp16(uint32_t dst, const void* src) {
    asm volatile("cp.async.cg.shared.global [%0], [%1], 16;" :: "r"(dst), "l"(src));
}
#define CP_COMMIT() asm volatile("cp.async.commit_group;" ::: "memory")
#define CP_WAIT(n)  asm volatile("cp.async.wait_group %0;" :: "n"(n) : "memory")

__device__ __forceinline__ void ldsm_x4(uint32_t& r0, uint32_t& r1, uint32_t& r2,
                                        uint32_t& r3, uint32_t a) {
    asm volatile("ldmatrix.sync.aligned.m8n8.x4.shared.b16 {%0,%1,%2,%3}, [%4];"
                 : "=r"(r0), "=r"(r1), "=r"(r2), "=r"(r3) : "r"(a));
}
__device__ __forceinline__ void mma16816(float* c, uint32_t a0, uint32_t a1,
                                         uint32_t a2, uint32_t a3,
                                         uint32_t b0, uint32_t b1) {
    asm volatile(
        "mma.sync.aligned.m16n8k16.row.col.f32.bf16.bf16.f32 "
        "{%0,%1,%2,%3}, {%4,%5,%6,%7}, {%8,%9}, {%0,%1,%2,%3};"
        : "+f"(c[0]), "+f"(c[1]), "+f"(c[2]), "+f"(c[3])
        : "r"(a0), "r"(a1), "r"(a2), "r"(a3), "r"(b0), "r"(b1));
}
__device__ __forceinline__ void ins3(float v, float& a, float& b, float& c) {
    if (v > c) {
        if (v > a)      { c = b; b = a; a = v; }
        else if (v > b) { c = b; b = v; }
        else            { c = v; }
    }
}

// ---------------------------------------------------------------------------
// Kernel 0: zero d_s (N-padding rows must stay inert)
// ---------------------------------------------------------------------------
__global__ void zero_kernel() {
    const size_t ns4 = sizeof(d_s) / 16;
    uint4 z = make_uint4(0, 0, 0, 0);
    for (size_t i = (size_t)blockIdx.x * blockDim.x + threadIdx.x;
         i < ns4; i += (size_t)gridDim.x * blockDim.x)
        ((uint4*)d_s)[i] = z;
}

// ---------------------------------------------------------------------------
// Kernel 1: fused L2-normalize + transpose [C,HW]->[HW,C] + bf16 convert.
// ---------------------------------------------------------------------------
__global__ void __launch_bounds__(256) convert_kernel(const float* __restrict__ x1,
                                                      const float* __restrict__ x2) {
    int bid = blockIdx.x;
    const float* src;
    __nv_bfloat16* dst;
    int m0;
    if (bid < 525) {
        int img = bid / 7; m0 = (bid % 7) * 64;
        src = x1 + (size_t)img * NC * NHW;
        dst = d_q + (size_t)img * NHW * NC;          // packed, no per-image pad
    } else {
        int sid = bid - 525;
        int img = sid / 7; m0 = (sid % 7) * 64;
        int w = img / 5, sh = img % 5;
        src = x2 + (size_t)img * NC * NHW;
        dst = d_s + ((size_t)w * SPAD + (size_t)sh * NHW) * NC;
    }
    int tid = threadIdx.x;
    int mx = tid & 63, cy = tid >> 6;

    __shared__ float sp[4][64];
    __shared__ float sinv[64];
    __shared__ __nv_bfloat16 st[64][72];

    float acc = 0.f;
    if (m0 + mx < NHW) {
        for (int c = cy; c < NC; c += 4) {
            float v = src[(size_t)c * NHW + m0 + mx];
            acc = fmaf(v, v, acc);
        }
    }
    sp[cy][mx] = acc;
    __syncthreads();
    if (tid < 64)
        sinv[tid] = rsqrtf(sp[0][tid] + sp[1][tid] + sp[2][tid] + sp[3][tid]);
    __syncthreads();

    int mr = tid >> 2, qt = tid & 3;
    for (int c0 = 0; c0 < NC; c0 += 64) {
#pragma unroll
        for (int j = 0; j < 16; j++) {
            int idx = j * 256 + tid;
            int cl = idx >> 6, mm = idx & 63;
            float v = (m0 + mm < NHW) ? src[(size_t)(c0 + cl) * NHW + m0 + mm] : 0.f;
            st[mm][cl] = __float2bfloat16(v * sinv[mm]);
        }
        __syncthreads();
        if (m0 + mr < NHW) {
            __nv_bfloat16 tmp[16];
#pragma unroll
            for (int i = 0; i < 16; i++) tmp[i] = st[mr][qt * 16 + i];
            __nv_bfloat16* drow = dst + (size_t)(m0 + mr) * NC + c0 + qt * 16;
            ((uint4*)drow)[0] = ((uint4*)tmp)[0];
            ((uint4*)drow)[1] = ((uint4*)tmp)[1];
        }
        __syncthreads();
    }
}

// ---------------------------------------------------------------------------
// Kernel 2: bf16 mma.sync GEMM + fused top-3 + per-row sum.
// CTA = (mtile, w). 128 threads = 2 warpM x 2 warpN, warp tile 64x64, BK=64.
// 180-chunk stream, 3-stage cp.async ring, one sync per chunk.
// 128 HMMA per 32 LDSM per chunk; 128 fp32 accums/thread.
// ---------------------------------------------------------------------------
__global__ void __launch_bounds__(128, 2) sim_kernel() {
    extern __shared__ char smem[];
    const uint32_t sbA = smem_u32(smem);
    const uint32_t sbB = sbA + SB_OFF;
    float (*smerge)[2][3] = (float(*)[2][3])(smem + MERGE_OFF);

    const int bid   = blockIdx.x;
    const int w     = bid % NWAY;
    const int mtile = bid / NWAY;
    const int tid   = threadIdx.x;
    const int wid   = tid >> 5;
    const int lane  = tid & 31;
    const int warpM = wid & 1;
    const int warpN = wid >> 1;
    const int g8    = lane >> 2;
    const int tig   = lane & 3;

    const __nv_bfloat16* Ab = d_q + (size_t)mtile * 128 * NC;
    const __nv_bfloat16* Bw = d_s + (size_t)w * SPAD * NC;

    // loader mapping: 1024 16B-vectors per array per chunk; 8 per thread per array
    const int lrow0 = tid >> 3;            // 0..15, step 16 per j
    const int lc8   = (tid & 7) * 8;       // col in bf16

    // ldmatrix coords
    const int arow = warpM * 64 + (lane & 15);
    const int acol = (lane >> 4) * 8;
    const int brow = warpN * 64 + ((lane >> 4) << 3) + (lane & 7);  // + nh*16
    const int bcol = ((lane >> 3) & 1) * 8;                          // + ks*16

    float t0[8], t1[8], t2[8];
#pragma unroll
    for (int s = 0; s < 8; s++) { t0[s] = t1[s] = t2[s] = -1e30f; }

    float acc[4][8][4];   // [mf][nf][frag]

    auto issue = [&](int g2) {
        if (g2 < TOTCH) {
            int nt2 = g2 / KCH, kc2 = g2 - nt2 * KCH;
            uint32_t so = (uint32_t)(g2 % 3) * STG_BYTES;
            const __nv_bfloat16* As = Ab + kc2 * BK;
            const __nv_bfloat16* Bs = Bw + (size_t)nt2 * 128 * NC + kc2 * BK;
            uint32_t sdst = so + (uint32_t)(lrow0 * SAS + lc8) * 2;
            const __nv_bfloat16* ag = As + (size_t)lrow0 * NC + lc8;
            const __nv_bfloat16* bg = Bs + (size_t)lrow0 * NC + lc8;
#pragma unroll
            for (int j = 0; j < 8; j++) {
                cp16(sbA + sdst, ag);
                cp16(sbB + sdst, bg);
                sdst += 16 * SAS * 2;
                ag += 16 * NC;
                bg += 16 * NC;
            }
        }
        CP_COMMIT();
    };

    issue(0);
    issue(1);

    for (int g = 0; g < TOTCH; g++) {
        const int nt = g / KCH;
        const int kc = g - nt * KCH;
        const uint32_t cso = (uint32_t)(g % 3) * STG_BYTES;

        CP_WAIT(1);           // chunk g landed
        __syncthreads();      // everyone done with stage (g+2)%3
        issue(g + 2);

        if (kc == 0) {
#pragma unroll
            for (int mf = 0; mf < 4; mf++)
#pragma unroll
                for (int nf = 0; nf < 8; nf++)
#pragma unroll
                    for (int j = 0; j < 4; j++) acc[mf][nf][j] = 0.f;
        }

#pragma unroll
        for (int ks = 0; ks < 4; ks++) {
            uint32_t a0[4], a1[4], a2[4], a3[4];
#pragma unroll
            for (int mf = 0; mf < 4; mf++) {
                uint32_t addr = sbA + cso +
                    (uint32_t)((arow + mf * 16) * SAS + ks * 16 + acol) * 2;
                ldsm_x4(a0[mf], a1[mf], a2[mf], a3[mf], addr);
            }
            uint32_t b[8][2];
#pragma unroll
            for (int nh = 0; nh < 4; nh++) {
                uint32_t addr = sbB + cso +
                    (uint32_t)((brow + nh * 16) * SAS + ks * 16 + bcol) * 2;
                uint32_t r0, r1, r2, r3;
                ldsm_x4(r0, r1, r2, r3, addr);
                b[nh * 2][0] = r0;     b[nh * 2][1] = r1;
                b[nh * 2 + 1][0] = r2; b[nh * 2 + 1][1] = r3;
            }
#pragma unroll
            for (int mf = 0; mf < 4; mf++)
#pragma unroll
                for (int nf = 0; nf < 8; nf++)
                    mma16816(acc[mf][nf], a0[mf], a1[mf], a2[mf], a3[mf],
                             b[nf][0], b[nf][1]);
        }

        if (kc == KCH - 1) {
            // fold this n-tile into running top-3 (mask N padding on last tile)
            const int climit = (nt == NT - 1) ? (NSD - (NT - 1) * 128) : 128;
#pragma unroll
            for (int mf = 0; mf < 4; mf++) {
                const int s0 = mf * 2, s1 = mf * 2 + 1;
#pragma unroll
                for (int nf = 0; nf < 8; nf++) {
                    const int colb = warpN * 64 + nf * 8 + tig * 2;
                    const bool u0 = colb < climit, u1 = colb + 1 < climit;
                    const float* c = acc[mf][nf];
                    if (u0) { ins3(c[0], t0[s0], t1[s0], t2[s0]);
                              ins3(c[2], t0[s1], t1[s1], t2[s1]); }
                    if (u1) { ins3(c[1], t0[s0], t1[s0], t2[s0]);
                              ins3(c[3], t0[s1], t1[s1], t2[s1]); }
                }
            }
        }
    }

    // intra-warp merge across the 4 lanes sharing each row
#pragma unroll
    for (int s = 0; s < 8; s++) {
#pragma unroll
        for (int d = 1; d <= 2; d <<= 1) {
            float m0 = __shfl_xor_sync(0xffffffffu, t0[s], d);
            float m1 = __shfl_xor_sync(0xffffffffu, t1[s], d);
            float m2 = __shfl_xor_sync(0xffffffffu, t2[s], d);
            ins3(m0, t0[s], t1[s], t2[s]);
            ins3(m1, t0[s], t1[s], t2[s]);
            ins3(m2, t0[s], t1[s], t2[s]);
        }
    }
    if (tig == 0) {
#pragma unroll
        for (int s = 0; s < 8; s++) {
            int row = warpM * 64 + (s >> 1) * 16 + (s & 1) * 8 + g8;
            smerge[row][warpN][0] = t0[s];
            smerge[row][warpN][1] = t1[s];
            smerge[row][warpN][2] = t2[s];
        }
    }
    __syncthreads();

    // merge the 2 N-warps per row; write per-row top-3 sum
    {
        int grow = mtile * 128 + tid;
        if (grow < MROWS) {
            float a = smerge[tid][0][0], b = smerge[tid][0][1], c = smerge[tid][0][2];
            ins3(smerge[tid][1][0], a, b, c);
            ins3(smerge[tid][1][1], a, b, c);
            ins3(smerge[tid][1][2], a, b, c);
            d_rowsum[(size_t)w * MPAD + grow] = a + b + c;
        }
    }
}

// ---------------------------------------------------------------------------
// Kernel 3: one warp per (q, w) sums its 441 row contributions.
// ---------------------------------------------------------------------------
__global__ void reduce_kernel(float* __restrict__ out) {
    int wi = (blockIdx.x * blockDim.x + threadIdx.x) >> 5;
    int lane = threadIdx.x & 31;
    if (wi >= NQ * NWAY) return;
    int q = wi / NWAY, w = wi % NWAY;
    const float* rs = d_rowsum + (size_t)w * MPAD + (size_t)q * NHW;
    float s = 0.f;
    for (int m = lane; m < NHW; m += 32) s += rs[m];
#pragma unroll
    for (int o = 16; o > 0; o >>= 1) s += __shfl_xor_sync(0xffffffffu, s, o);
    if (lane == 0) out[wi] = s;
}

// ---------------------------------------------------------------------------
extern "C" void kernel_launch(void* const* d_in, const int* in_sizes, int n_in,
                              void* d_out, int out_size) {
    const float* x1 = (const float*)d_in[0];   // [75, 640, 21, 21]
    const float* x2 = (const float*)d_in[1];   // [25, 640, 21, 21]
    float* out = (float*)d_out;                // [75, 5]

    cudaFuncSetAttribute(sim_kernel, cudaFuncAttributeMaxDynamicSharedMemorySize,
                         SMEM_TOTAL);

    zero_kernel<<<512, 256>>>();
    convert_kernel<<<700, 256>>>(x1, x2);
    sim_kernel<<<MTILES * NWAY, 128, SMEM_TOTAL>>>();
    reduce_kernel<<<(NQ * NWAY * 32 + 255) / 256, 256>>>(out);
}